// round 13
// baseline (speedup 1.0000x reference)
#include <cuda_runtime.h>
#include <cuda_fp16.h>
#include <math.h>
#include <stdint.h>

// ---------------- problem constants ----------------
static constexpr int kIN  = 128;
static constexpr int kH   = 4;
static constexpr int kC   = 64;
static constexpr int kHC  = 256;
static constexpr int kOUT = 512;
static constexpr int MAXN  = 50000;
static constexpr int MAXET = 850000;

// ---------------- scratch ----------------
__device__ float g_bufA[(size_t)MAXN * kHC];
__device__ float g_bufB[(size_t)MAXN * kHC];
__device__ float g_bufC[(size_t)MAXN * kHC];
__device__ float g_attn[6 * (size_t)MAXN * kH];
__device__ int   g_rowptr[MAXN + 1];
__device__ int   g_deg[MAXN];
__device__ int   g_cur[MAXN];
__device__ int   g_adj[MAXET];
__device__ int   g_bsum[256];

// ---------------- helpers ----------------
__device__ __forceinline__ uint32_t pack_half2(float x, float y) {
    __half2 h = __float22half2_rn(make_float2(x, y));
    return *(uint32_t*)&h;
}

__device__ __forceinline__ void mma_f16_16x8x16(float* c, const uint32_t* a, const uint32_t* b) {
    asm volatile(
        "mma.sync.aligned.m16n8k16.row.col.f32.f16.f16.f32 "
        "{%0,%1,%2,%3}, {%4,%5,%6,%7}, {%8,%9}, {%0,%1,%2,%3};"
        : "+f"(c[0]), "+f"(c[1]), "+f"(c[2]), "+f"(c[3])
        : "r"(a[0]), "r"(a[1]), "r"(a[2]), "r"(a[3]), "r"(b[0]), "r"(b[1]));
}

__device__ __forceinline__ float edge_alpha(float as_v, float ad)
{
    float l = as_v + ad;
    l = (l > 0.f) ? l : 0.2f * l;
    return __expf(l);
}

__device__ __forceinline__ void acc8_half(float* acc, float a, uint4 r)
{
    const __half2* hp = (const __half2*)&r;
#pragma unroll
    for (int i = 0; i < 4; i++) {
        float2 f = __half22float2(hp[i]);
        acc[2 * i]     += a * f.x;
        acc[2 * i + 1] += a * f.y;
    }
}

// ---------------- fp16 mma.sync GEMM with fused attn epilogue (standalone) ----------------
template <int BN, int AH, bool HIN, bool HOUT>
__global__ __launch_bounds__(256)
void tgemm_kernel(const void* __restrict__ Ain, const float* __restrict__ W,
                  void* __restrict__ Cout, int M, int K, int Nc,
                  const float* __restrict__ bias, int do_relu,
                  const float* __restrict__ avs, const float* __restrict__ avd,
                  float* __restrict__ as_n, float* __restrict__ ad_n)
{
    static constexpr int SAW = 20;
    static constexpr int SBW = BN + 4;
    static constexpr int NT  = BN / 32;
    static constexpr int NB2 = BN / 16;
    static constexpr int LOG2BN = (BN == 128) ? 7 : 6;

    __shared__ uint32_t sA[128 * SAW];
    __shared__ uint32_t sB[16 * SBW];

    const int tid = threadIdx.x;
    const int wid = tid >> 5;
    const int lid = tid & 31;
    const int g   = lid >> 2;
    const int tig = lid & 3;
    const int warp_m = wid & 1;
    const int warp_n = wid >> 1;

    const int rowBase = blockIdx.y * 128;
    const int colBase = blockIdx.x * BN;

    float acc[4][NT][4];
#pragma unroll
    for (int mt = 0; mt < 4; mt++)
#pragma unroll
        for (int nt = 0; nt < NT; nt++)
#pragma unroll
            for (int i = 0; i < 4; i++) acc[mt][nt][i] = 0.f;

    float4 aRegF[4];
    uint4  aRegH[2];
    float2 wReg[NB2];

    auto loadA = [&](int k0) {
        if (HIN) {
            const __half* A = (const __half*)Ain;
#pragma unroll
            for (int i = 0; i < 2; i++) {
                int idx = tid + 256 * i;
                int m = idx >> 2, c8 = idx & 3;
                int gr = rowBase + m;
                aRegH[i] = (gr < M) ? *(const uint4*)(A + (size_t)gr * K + k0 + c8 * 8)
                                    : make_uint4(0u, 0u, 0u, 0u);
            }
        } else {
            const float* A = (const float*)Ain;
#pragma unroll
            for (int i = 0; i < 4; i++) {
                int idx = tid + 256 * i;
                int m = idx >> 3, c4 = idx & 7;
                int gr = rowBase + m;
                aRegF[i] = (gr < M) ? *(const float4*)(A + (size_t)gr * K + k0 + c4 * 4)
                                    : make_float4(0.f, 0.f, 0.f, 0.f);
            }
        }
    };
    auto loadW = [&](int k0) {
#pragma unroll
        for (int i = 0; i < NB2; i++) {
            int idx = tid + 256 * i;
            int n  = idx & (BN - 1);
            int k2 = idx >> LOG2BN;
            wReg[i].x = W[(size_t)(k0 + 2 * k2)     * Nc + colBase + n];
            wReg[i].y = W[(size_t)(k0 + 2 * k2 + 1) * Nc + colBase + n];
        }
    };
    auto stsTiles = [&]() {
        if (HIN) {
#pragma unroll
            for (int i = 0; i < 2; i++) {
                int idx = tid + 256 * i;
                int m = idx >> 2, c8 = idx & 3;
                *(uint4*)(sA + m * SAW + c8 * 4) = aRegH[i];
            }
        } else {
#pragma unroll
            for (int i = 0; i < 4; i++) {
                int idx = tid + 256 * i;
                int m = idx >> 3, c4 = idx & 7;
                float4 v = aRegF[i];
                uint2 w;
                w.x = pack_half2(v.x, v.y);
                w.y = pack_half2(v.z, v.w);
                *(uint2*)(sA + m * SAW + c4 * 2) = w;
            }
        }
#pragma unroll
        for (int i = 0; i < NB2; i++) {
            int idx = tid + 256 * i;
            int n  = idx & (BN - 1);
            int k2 = idx >> LOG2BN;
            sB[k2 * SBW + n] = pack_half2(wReg[i].x, wReg[i].y);
        }
    };

    const int nchunk = K / 32;
    loadA(0);
    loadW(0);

    for (int ch = 0; ch < nchunk; ch++) {
        stsTiles();
        __syncthreads();
        if (ch + 1 < nchunk) { loadA((ch + 1) * 32); loadW((ch + 1) * 32); }

#pragma unroll
        for (int kk = 0; kk < 2; kk++) {
            const int kb2 = kk * 8;
            uint32_t afr[4][4];
#pragma unroll
            for (int mt = 0; mt < 4; mt++) {
                int m = warp_m * 64 + mt * 16 + g;
                afr[mt][0] = sA[(m)     * SAW + kb2 + tig];
                afr[mt][1] = sA[(m + 8) * SAW + kb2 + tig];
                afr[mt][2] = sA[(m)     * SAW + kb2 + tig + 4];
                afr[mt][3] = sA[(m + 8) * SAW + kb2 + tig + 4];
            }
            uint32_t bfr[NT][2];
#pragma unroll
            for (int nt = 0; nt < NT; nt++) {
                int n = warp_n * (BN / 4) + nt * 8 + g;
                bfr[nt][0] = sB[(kb2 + tig)     * SBW + n];
                bfr[nt][1] = sB[(kb2 + tig + 4) * SBW + n];
            }
#pragma unroll
            for (int mt = 0; mt < 4; mt++)
#pragma unroll
                for (int nt = 0; nt < NT; nt++)
                    mma_f16_16x8x16(acc[mt][nt], afr[mt], bfr[nt]);
        }
        __syncthreads();
    }

    if (AH > 0) {
        const int h = (AH == 1) ? 0 : ((colBase + warp_n * (BN / 4)) >> 6);
#pragma unroll
        for (int mt = 0; mt < 4; mt++) {
            float s0 = 0.f, s1 = 0.f, d0 = 0.f, d1 = 0.f;
#pragma unroll
            for (int nt = 0; nt < NT; nt++) {
                int col = colBase + warp_n * (BN / 4) + nt * 8 + tig * 2;
                float a0 = avs[col], a1 = avs[col + 1];
                float b0 = avd[col], b1 = avd[col + 1];
                s0 += acc[mt][nt][0] * a0 + acc[mt][nt][1] * a1;
                s1 += acc[mt][nt][2] * a0 + acc[mt][nt][3] * a1;
                d0 += acc[mt][nt][0] * b0 + acc[mt][nt][1] * b1;
                d1 += acc[mt][nt][2] * b0 + acc[mt][nt][3] * b1;
            }
#pragma unroll
            for (int off = 1; off <= 2; off <<= 1) {
                s0 += __shfl_xor_sync(0xFFFFFFFFu, s0, off);
                s1 += __shfl_xor_sync(0xFFFFFFFFu, s1, off);
                d0 += __shfl_xor_sync(0xFFFFFFFFu, d0, off);
                d1 += __shfl_xor_sync(0xFFFFFFFFu, d1, off);
            }
            if (tig == 0) {
                int row0 = rowBase + warp_m * 64 + mt * 16 + g;
                int row1 = row0 + 8;
                if (row0 < M) {
                    atomicAdd(&as_n[(size_t)row0 * AH + h], s0);
                    atomicAdd(&ad_n[(size_t)row0 * AH + h], d0);
                }
                if (row1 < M) {
                    atomicAdd(&as_n[(size_t)row1 * AH + h], s1);
                    atomicAdd(&ad_n[(size_t)row1 * AH + h], d1);
                }
            }
        }
    }

#pragma unroll
    for (int mt = 0; mt < 4; mt++) {
        int row0 = rowBase + warp_m * 64 + mt * 16 + g;
        int row1 = row0 + 8;
#pragma unroll
        for (int nt = 0; nt < NT; nt++) {
            int col = colBase + warp_n * (BN / 4) + nt * 8 + tig * 2;
            float bx = 0.f, by = 0.f;
            if (bias) { bx = bias[col]; by = bias[col + 1]; }
            float2 v0 = make_float2(acc[mt][nt][0] + bx, acc[mt][nt][1] + by);
            float2 v1 = make_float2(acc[mt][nt][2] + bx, acc[mt][nt][3] + by);
            if (do_relu) {
                v0.x = fmaxf(v0.x, 0.f); v0.y = fmaxf(v0.y, 0.f);
                v1.x = fmaxf(v1.x, 0.f); v1.y = fmaxf(v1.y, 0.f);
            }
            if (HOUT) {
                __half2* Ch = (__half2*)Cout;
                if (row0 < M) Ch[((size_t)row0 * Nc + col) >> 1] = __float22half2_rn(v0);
                if (row1 < M) Ch[((size_t)row1 * Nc + col) >> 1] = __float22half2_rn(v1);
            } else {
                float* Cf = (float*)Cout;
                if (row0 < M) *(float2*)(Cf + (size_t)row0 * Nc + col) = v0;
                if (row1 < M) *(float2*)(Cf + (size_t)row1 * Nc + col) = v1;
            }
        }
    }
}

// ---------------- FUSED gather + GEMM ----------------
// Phase 1: each warp gathers 16 nodes (input HC=256 half) -> biased+relu half A tile in smem.
// Phase 2: fp16 MMA with A resident; NBLK column blocks processed sequentially.
template <int BN, int NBLK, int AH>
__global__ __launch_bounds__(256)
void fused_kernel(const int* __restrict__ rowptr, const int* __restrict__ adj,
                  const __half* __restrict__ xl,
                  const float* __restrict__ as_in, const float* __restrict__ ad_in,
                  const float* __restrict__ bias_in,
                  const float* __restrict__ W, __half* __restrict__ Cout,
                  int M, int Nc,
                  const float* __restrict__ avs, const float* __restrict__ avd,
                  float* __restrict__ as_out, float* __restrict__ ad_out)
{
    static constexpr int SAW = 132;          // 128 data words + 4 pad
    static constexpr int SBW = BN + 4;
    static constexpr int NT  = BN / 32;
    static constexpr int NB2 = BN / 16;
    static constexpr int LOG2BN = (BN == 128) ? 7 : 6;

    extern __shared__ uint32_t smem[];
    uint32_t* sA = smem;                     // 128 * SAW
    uint32_t* sB = smem + 128 * SAW;         // 16 * SBW

    const int tid = threadIdx.x;
    const int wid = tid >> 5;
    const int lid = tid & 31;
    const int g   = lid >> 2;
    const int tig = lid & 3;
    const int warp_m = wid & 1;
    const int warp_n = wid >> 1;

    const int rowBase = blockIdx.x * 128;

    // ---- phase 1: gather 16 nodes per warp ----
    {
        const int h   = lid >> 3;
        const int col = lid * 8;
        for (int t = 0; t < 16; t++) {
            int m = wid * 16 + t;
            int node = rowBase + m;
            uint32_t o[4] = {0u, 0u, 0u, 0u};
            if (node < M) {
                const float ad = ad_in[(size_t)node * 4 + h];
                float acc[8];
#pragma unroll
                for (int i = 0; i < 8; i++) acc[i] = 0.f;
                float den = 0.f;
                const int beg = rowptr[node], end = rowptr[node + 1];
                int j = beg;
                for (; j + 3 < end; j += 4) {
                    int s0 = adj[j], s1 = adj[j + 1], s2 = adj[j + 2], s3 = adj[j + 3];
                    float a0 = edge_alpha(as_in[(size_t)s0 * 4 + h], ad);
                    float a1 = edge_alpha(as_in[(size_t)s1 * 4 + h], ad);
                    float a2 = edge_alpha(as_in[(size_t)s2 * 4 + h], ad);
                    float a3 = edge_alpha(as_in[(size_t)s3 * 4 + h], ad);
                    uint4 r0 = *(const uint4*)(xl + (size_t)s0 * 256 + col);
                    uint4 r1 = *(const uint4*)(xl + (size_t)s1 * 256 + col);
                    uint4 r2 = *(const uint4*)(xl + (size_t)s2 * 256 + col);
                    uint4 r3 = *(const uint4*)(xl + (size_t)s3 * 256 + col);
                    den += (a0 + a1) + (a2 + a3);
                    acc8_half(acc, a0, r0);
                    acc8_half(acc, a1, r1);
                    acc8_half(acc, a2, r2);
                    acc8_half(acc, a3, r3);
                }
                for (; j < end; j++) {
                    int s = adj[j];
                    float a = edge_alpha(as_in[(size_t)s * 4 + h], ad);
                    uint4 r = *(const uint4*)(xl + (size_t)s * 256 + col);
                    den += a;
                    acc8_half(acc, a, r);
                }
                float inv = 1.f / (den + 1e-16f);
#pragma unroll
                for (int i = 0; i < 4; i++) {
                    float fx = fmaxf(acc[2 * i]     * inv + bias_in[col + 2 * i],     0.f);
                    float fy = fmaxf(acc[2 * i + 1] * inv + bias_in[col + 2 * i + 1], 0.f);
                    o[i] = pack_half2(fx, fy);
                }
            }
            *(uint4*)(sA + m * SAW + lid * 4) = make_uint4(o[0], o[1], o[2], o[3]);
        }
    }
    __syncthreads();

    // ---- phase 2: GEMM over NBLK column blocks ----
    float2 wReg[NB2];
    for (int nb = 0; nb < NBLK; nb++) {
        const int colBase = nb * BN;

        float acc[4][NT][4];
#pragma unroll
        for (int mt = 0; mt < 4; mt++)
#pragma unroll
            for (int nt = 0; nt < NT; nt++)
#pragma unroll
                for (int i = 0; i < 4; i++) acc[mt][nt][i] = 0.f;

        auto loadW = [&](int k0) {
#pragma unroll
            for (int i = 0; i < NB2; i++) {
                int idx = tid + 256 * i;
                int n  = idx & (BN - 1);
                int k2 = idx >> LOG2BN;
                wReg[i].x = W[(size_t)(k0 + 2 * k2)     * Nc + colBase + n];
                wReg[i].y = W[(size_t)(k0 + 2 * k2 + 1) * Nc + colBase + n];
            }
        };
        loadW(0);

        for (int ch = 0; ch < 8; ch++) {
            __syncthreads();                 // protect sB before overwrite
#pragma unroll
            for (int i = 0; i < NB2; i++) {
                int idx = tid + 256 * i;
                int n  = idx & (BN - 1);
                int k2 = idx >> LOG2BN;
                sB[k2 * SBW + n] = pack_half2(wReg[i].x, wReg[i].y);
            }
            __syncthreads();
            if (ch + 1 < 8) loadW((ch + 1) * 32);

            const int aOff = ch * 16;
#pragma unroll
            for (int kk = 0; kk < 2; kk++) {
                const int kb2 = kk * 8;
                uint32_t afr[4][4];
#pragma unroll
                for (int mt = 0; mt < 4; mt++) {
                    int m = warp_m * 64 + mt * 16 + g;
                    afr[mt][0] = sA[(m)     * SAW + aOff + kb2 + tig];
                    afr[mt][1] = sA[(m + 8) * SAW + aOff + kb2 + tig];
                    afr[mt][2] = sA[(m)     * SAW + aOff + kb2 + tig + 4];
                    afr[mt][3] = sA[(m + 8) * SAW + aOff + kb2 + tig + 4];
                }
                uint32_t bfr[NT][2];
#pragma unroll
                for (int nt = 0; nt < NT; nt++) {
                    int n = warp_n * (BN / 4) + nt * 8 + g;
                    bfr[nt][0] = sB[(kb2 + tig)     * SBW + n];
                    bfr[nt][1] = sB[(kb2 + tig + 4) * SBW + n];
                }
#pragma unroll
                for (int mt = 0; mt < 4; mt++)
#pragma unroll
                    for (int nt = 0; nt < NT; nt++)
                        mma_f16_16x8x16(acc[mt][nt], afr[mt], bfr[nt]);
            }
        }

        // attn partials for this column block
        {
            const int h = (AH == 1) ? 0 : ((colBase + warp_n * (BN / 4)) >> 6);
#pragma unroll
            for (int mt = 0; mt < 4; mt++) {
                float s0 = 0.f, s1 = 0.f, d0 = 0.f, d1 = 0.f;
#pragma unroll
                for (int nt = 0; nt < NT; nt++) {
                    int col = colBase + warp_n * (BN / 4) + nt * 8 + tig * 2;
                    float a0 = avs[col], a1 = avs[col + 1];
                    float b0 = avd[col], b1 = avd[col + 1];
                    s0 += acc[mt][nt][0] * a0 + acc[mt][nt][1] * a1;
                    s1 += acc[mt][nt][2] * a0 + acc[mt][nt][3] * a1;
                    d0 += acc[mt][nt][0] * b0 + acc[mt][nt][1] * b1;
                    d1 += acc[mt][nt][2] * b0 + acc[mt][nt][3] * b1;
                }
#pragma unroll
                for (int off = 1; off <= 2; off <<= 1) {
                    s0 += __shfl_xor_sync(0xFFFFFFFFu, s0, off);
                    s1 += __shfl_xor_sync(0xFFFFFFFFu, s1, off);
                    d0 += __shfl_xor_sync(0xFFFFFFFFu, d0, off);
                    d1 += __shfl_xor_sync(0xFFFFFFFFu, d1, off);
                }
                if (tig == 0) {
                    int row0 = rowBase + warp_m * 64 + mt * 16 + g;
                    int row1 = row0 + 8;
                    if (row0 < M) {
                        atomicAdd(&as_out[(size_t)row0 * AH + h], s0);
                        atomicAdd(&ad_out[(size_t)row0 * AH + h], d0);
                    }
                    if (row1 < M) {
                        atomicAdd(&as_out[(size_t)row1 * AH + h], s1);
                        atomicAdd(&ad_out[(size_t)row1 * AH + h], d1);
                    }
                }
            }
        }

        // store C (half, no bias/relu — raw xl of next layer)
#pragma unroll
        for (int mt = 0; mt < 4; mt++) {
            int row0 = rowBase + warp_m * 64 + mt * 16 + g;
            int row1 = row0 + 8;
#pragma unroll
            for (int nt = 0; nt < NT; nt++) {
                int col = colBase + warp_n * (BN / 4) + nt * 8 + tig * 2;
                __half2* Ch = (__half2*)Cout;
                if (row0 < M)
                    Ch[((size_t)row0 * Nc + col) >> 1] =
                        __float22half2_rn(make_float2(acc[mt][nt][0], acc[mt][nt][1]));
                if (row1 < M)
                    Ch[((size_t)row1 * Nc + col) >> 1] =
                        __float22half2_rn(make_float2(acc[mt][nt][2], acc[mt][nt][3]));
            }
        }
    }
}

// ---------------- CSR build ----------------
__global__ void count_kernel(const int* __restrict__ ei, int E, int N, int* __restrict__ deg)
{
    int base = (blockIdx.x * blockDim.x + threadIdx.x) * 4;
    int ET = E + N;
    if (base >= ET) return;
    if (base + 3 < E) {
        int4 d4 = *(const int4*)(ei + E + base);
        atomicAdd(&deg[d4.x], 1);
        atomicAdd(&deg[d4.y], 1);
        atomicAdd(&deg[d4.z], 1);
        atomicAdd(&deg[d4.w], 1);
    } else {
#pragma unroll
        for (int k = 0; k < 4; k++) {
            int e = base + k;
            if (e >= ET) break;
            int d = (e < E) ? ei[E + e] : (e - E);
            atomicAdd(&deg[d], 1);
        }
    }
}

__global__ void scan1_kernel(const int* __restrict__ deg, int* __restrict__ rowptr,
                             int* __restrict__ bsum, int N)
{
    __shared__ int sh[1024];
    int i = blockIdx.x * 1024 + threadIdx.x;
    int v = (i < N) ? deg[i] : 0;
    sh[threadIdx.x] = v;
    __syncthreads();
#pragma unroll
    for (int off = 1; off < 1024; off <<= 1) {
        int t = (threadIdx.x >= off) ? sh[threadIdx.x - off] : 0;
        __syncthreads();
        sh[threadIdx.x] += t;
        __syncthreads();
    }
    if (i < N) rowptr[i + 1] = sh[threadIdx.x];
    if (threadIdx.x == 1023) bsum[blockIdx.x] = sh[1023];
}

__global__ void scan3_kernel(int* __restrict__ rowptr, const int* __restrict__ bsum,
                             const int* __restrict__ deg, int* __restrict__ cur, int N)
{
    int off = 0;
    for (int b = 0; b < blockIdx.x; b++) off += bsum[b];
    int i = blockIdx.x * 1024 + threadIdx.x;
    if (i < N) {
        int v = rowptr[i + 1] + off;
        rowptr[i + 1] = v;
        cur[i] = v - deg[i];
    }
    if (i == 0) rowptr[0] = 0;
}

__global__ void fill_kernel(const int* __restrict__ ei, int E, int N,
                            int* __restrict__ cur, int* __restrict__ adj)
{
    int base = (blockIdx.x * blockDim.x + threadIdx.x) * 4;
    int ET = E + N;
    if (base >= ET) return;
    if (base + 3 < E) {
        int4 s4 = *(const int4*)(ei + base);
        int4 d4 = *(const int4*)(ei + E + base);
        int p0 = atomicAdd(&cur[d4.x], 1);
        int p1 = atomicAdd(&cur[d4.y], 1);
        int p2 = atomicAdd(&cur[d4.z], 1);
        int p3 = atomicAdd(&cur[d4.w], 1);
        adj[p0] = s4.x;
        adj[p1] = s4.y;
        adj[p2] = s4.z;
        adj[p3] = s4.w;
    } else {
#pragma unroll
        for (int k = 0; k < 4; k++) {
            int e = base + k;
            if (e >= ET) break;
            int s, d;
            if (e < E) { s = ei[e]; d = ei[E + e]; } else { s = d = e - E; }
            int pos = atomicAdd(&cur[d], 1);
            adj[pos] = s;
        }
    }
}

// ---------------- gather1 (layer 3, C=64): one warp per node ----------------
__global__ __launch_bounds__(256) void gat_gather1_kernel(
    const int* __restrict__ rowptr, const int* __restrict__ adj,
    const __half* __restrict__ xl,
    const float* __restrict__ as_n, const float* __restrict__ ad_n,
    const float* __restrict__ bias, __half* __restrict__ out, int N)
{
    int w = (blockIdx.x * blockDim.x + threadIdx.x) >> 5;
    int lane = threadIdx.x & 31;
    if (w >= N) return;

    const int col = lane * 2;
    const float ad = ad_n[w];

    float acc0 = 0.f, acc1 = 0.f, den = 0.f;

    const int beg = rowptr[w], end = rowptr[w + 1];
    int j = beg;
    for (; j + 3 < end; j += 4) {
        int s0 = adj[j], s1 = adj[j + 1], s2 = adj[j + 2], s3 = adj[j + 3];
        float a0 = edge_alpha(as_n[s0], ad);
        float a1 = edge_alpha(as_n[s1], ad);
        float a2 = edge_alpha(as_n[s2], ad);
        float a3 = edge_alpha(as_n[s3], ad);
        float2 f0 = __half22float2(*(const __half2*)(xl + (size_t)s0 * 64 + col));
        float2 f1 = __half22float2(*(const __half2*)(xl + (size_t)s1 * 64 + col));
        float2 f2 = __half22float2(*(const __half2*)(xl + (size_t)s2 * 64 + col));
        float2 f3 = __half22float2(*(const __half2*)(xl + (size_t)s3 * 64 + col));
        den += (a0 + a1) + (a2 + a3);
        acc0 += a0 * f0.x + a1 * f1.x + a2 * f2.x + a3 * f3.x;
        acc1 += a0 * f0.y + a1 * f1.y + a2 * f2.y + a3 * f3.y;
    }
    for (; j < end; j++) {
        int s = adj[j];
        float a = edge_alpha(as_n[s], ad);
        float2 f = __half22float2(*(const __half2*)(xl + (size_t)s * 64 + col));
        den += a;
        acc0 += a * f.x;
        acc1 += a * f.y;
    }

    float inv = 1.f / (den + 1e-16f);
    float2 f;
    f.x = fmaxf(acc0 * inv + bias[col + 0], 0.f);
    f.y = fmaxf(acc1 * inv + bias[col + 1], 0.f);
    *(__half2*)(out + (size_t)w * 64 + col) = __float22half2_rn(f);
}

// ---------------- host orchestration ----------------
extern "C" void kernel_launch(void* const* d_in, const int* in_sizes, int n_in,
                              void* d_out, int out_size)
{
    const float* x   = (const float*)d_in[0];
    const int*   ei  = (const int*)d_in[1];
    const float* W1  = (const float*)d_in[2];
    const float* as1 = (const float*)d_in[3];
    const float* ad1 = (const float*)d_in[4];
    const float* b1  = (const float*)d_in[5];
    const float* W2  = (const float*)d_in[6];
    const float* as2 = (const float*)d_in[7];
    const float* ad2 = (const float*)d_in[8];
    const float* b2  = (const float*)d_in[9];
    const float* W3  = (const float*)d_in[10];
    const float* as3 = (const float*)d_in[11];
    const float* ad3 = (const float*)d_in[12];
    const float* b3  = (const float*)d_in[13];
    const float* Wfc = (const float*)d_in[14];
    const float* bfc = (const float*)d_in[15];
    float* out = (float*)d_out;

    int N  = in_sizes[0] / kIN;
    int E  = in_sizes[1] / 2;
    int ET = E + N;

    float *bufA, *bufB, *bufC, *attn;
    int *rowptr, *deg, *cur, *adj, *bsum;
    cudaGetSymbolAddress((void**)&bufA, g_bufA);
    cudaGetSymbolAddress((void**)&bufB, g_bufB);
    cudaGetSymbolAddress((void**)&bufC, g_bufC);
    cudaGetSymbolAddress((void**)&attn, g_attn);
    cudaGetSymbolAddress((void**)&rowptr, g_rowptr);
    cudaGetSymbolAddress((void**)&deg,    g_deg);
    cudaGetSymbolAddress((void**)&cur,    g_cur);
    cudaGetSymbolAddress((void**)&adj,    g_adj);
    cudaGetSymbolAddress((void**)&bsum,   g_bsum);

    size_t NH = (size_t)N * kH;
    float* pas1 = attn;
    float* pad1 = attn + NH;
    float* pas2 = attn + 2 * NH;
    float* pad2 = attn + 3 * NH;
    float* pas3 = attn + 4 * NH;
    float* pad3 = attn + 5 * NH;

    __half* bufAh = (__half*)bufA;
    __half* bufBh = (__half*)bufB;
    __half* bufCh = (__half*)bufC;

    int edge4Blocks = (ET + 1023) / 1024;
    int g1Blocks = (N + 7) / 8;
    int scanBlocks = (N + 1023) / 1024;
    int rowTiles = (N + 127) / 128;

    dim3 grid256(2, rowTiles);
    dim3 gridFC(4, rowTiles);

    static constexpr int kSmemF1 = (128 * 132 + 16 * 132) * 4;   // 76032
    static constexpr int kSmemF2 = (128 * 132 + 16 * 68) * 4;    // 71936

    static cudaStream_t s2 = nullptr;
    static cudaEvent_t evFork = nullptr, evJoin = nullptr;
    if (!s2) {
        cudaStreamCreateWithFlags(&s2, cudaStreamNonBlocking);
        cudaEventCreateWithFlags(&evFork, cudaEventDisableTiming);
        cudaEventCreateWithFlags(&evJoin, cudaEventDisableTiming);
        cudaFuncSetAttribute(fused_kernel<128, 2, 4>,
                             cudaFuncAttributeMaxDynamicSharedMemorySize, kSmemF1);
        cudaFuncSetAttribute(fused_kernel<64, 1, 1>,
                             cudaFuncAttributeMaxDynamicSharedMemorySize, kSmemF2);
    }

    // attn zeroing precedes all epilogue atomics (main stream)
    cudaMemsetAsync(attn, 0, 6 * NH * sizeof(float));
    cudaEventRecord(evFork, 0);
    cudaStreamWaitEvent(s2, evFork, 0);

    // ---- CSR build on s2 (overlaps GEMM1) ----
    cudaMemsetAsync(deg, 0, (size_t)N * sizeof(int), s2);
    count_kernel<<<edge4Blocks, 256, 0, s2>>>(ei, E, N, deg);
    scan1_kernel<<<scanBlocks, 1024, 0, s2>>>(deg, rowptr, bsum, N);
    scan3_kernel<<<scanBlocks, 1024, 0, s2>>>(rowptr, bsum, deg, cur, N);
    fill_kernel<<<edge4Blocks, 256, 0, s2>>>(ei, E, N, cur, adj);
    cudaEventRecord(evJoin, s2);

    // ---- layer 1 GEMM: x -> bufA (xl1 half) + attn1 ----
    tgemm_kernel<128, 4, false, true><<<grid256, 256>>>(
        x, W1, bufA, N, kIN, kHC, nullptr, 0, as1, ad1, pas1, pad1);
    cudaStreamWaitEvent(0, evJoin, 0);

    // ---- fused boundary 1: gather(xl1) + GEMM W2 -> bufB (xl2) + attn2 ----
    fused_kernel<128, 2, 4><<<rowTiles, 256, kSmemF1>>>(
        rowptr, adj, bufAh, pas1, pad1, b1, W2, bufBh, N, kHC, as2, ad2, pas2, pad2);

    // ---- fused boundary 2: gather(xl2) + GEMM W3 -> bufA (xl3) + attn3 ----
    fused_kernel<64, 1, 1><<<rowTiles, 256, kSmemF2>>>(
        rowptr, adj, bufBh, pas2, pad2, b2, W3, bufAh, N, kC, as3, ad3, pas3, pad3);

    // ---- layer 3 gather: xl3 -> bufC (h3 half) ----
    gat_gather1_kernel<<<g1Blocks, 256>>>(rowptr, adj, bufAh, pas3, pad3, b3, bufCh, N);

    // ---- final fc: bufC @ Wfc -> out (fp32, bias+relu) ----
    tgemm_kernel<128, 0, true, false><<<gridFC, 256>>>(
        bufCh, Wfc, out, N, kC, kOUT, bfc, 1, nullptr, nullptr, nullptr, nullptr);
}

// round 15
// speedup vs baseline: 1.2258x; 1.2258x over previous
#include <cuda_runtime.h>
#include <cuda_fp16.h>
#include <math.h>
#include <stdint.h>

// ---------------- problem constants ----------------
static constexpr int kIN  = 128;
static constexpr int kH   = 4;
static constexpr int kC   = 64;
static constexpr int kHC  = 256;
static constexpr int kOUT = 512;
static constexpr int MAXN  = 50000;
static constexpr int MAXET = 850000;

// ---------------- scratch ----------------
__device__ float g_bufA[(size_t)MAXN * kHC];
__device__ float g_bufB[(size_t)MAXN * kHC];
__device__ float g_bufC[(size_t)MAXN * kHC];
__device__ float g_attn[6 * (size_t)MAXN * kH];
__device__ int   g_rowptr[MAXN + 1];
__device__ int   g_deg[MAXN];
__device__ int   g_cur[MAXN];
__device__ int   g_adj[MAXET];
__device__ int   g_bsum[256];

// ---------------- helpers ----------------
__device__ __forceinline__ uint32_t pack_half2(float x, float y) {
    __half2 h = __float22half2_rn(make_float2(x, y));
    return *(uint32_t*)&h;
}

__device__ __forceinline__ void mma_f16_16x8x16(float* c, const uint32_t* a, const uint32_t* b) {
    asm volatile(
        "mma.sync.aligned.m16n8k16.row.col.f32.f16.f16.f32 "
        "{%0,%1,%2,%3}, {%4,%5,%6,%7}, {%8,%9}, {%0,%1,%2,%3};"
        : "+f"(c[0]), "+f"(c[1]), "+f"(c[2]), "+f"(c[3])
        : "r"(a[0]), "r"(a[1]), "r"(a[2]), "r"(a[3]), "r"(b[0]), "r"(b[1]));
}

__device__ __forceinline__ float edge_alpha(float as_v, float ad)
{
    float l = as_v + ad;
    l = (l > 0.f) ? l : 0.2f * l;
    return __expf(l);
}

__device__ __forceinline__ void acc8_half(float* acc, float a, uint4 r)
{
    const __half2* hp = (const __half2*)&r;
#pragma unroll
    for (int i = 0; i < 4; i++) {
        float2 f = __half22float2(hp[i]);
        acc[2 * i]     += a * f.x;
        acc[2 * i + 1] += a * f.y;
    }
}

// ---------------- fp16 mma.sync GEMM with fused attn epilogue ----------------
template <int BN, int AH, bool HIN, bool HOUT>
__global__ __launch_bounds__(256)
void tgemm_kernel(const void* __restrict__ Ain, const float* __restrict__ W,
                  void* __restrict__ Cout, int M, int K, int Nc,
                  const float* __restrict__ bias, int do_relu,
                  const float* __restrict__ avs, const float* __restrict__ avd,
                  float* __restrict__ as_n, float* __restrict__ ad_n)
{
    static constexpr int SAW = 20;
    static constexpr int SBW = BN + 4;
    static constexpr int NT  = BN / 32;
    static constexpr int NB2 = BN / 16;
    static constexpr int LOG2BN = (BN == 128) ? 7 : 6;

    __shared__ uint32_t sA[128 * SAW];
    __shared__ uint32_t sB[16 * SBW];

    const int tid = threadIdx.x;
    const int wid = tid >> 5;
    const int lid = tid & 31;
    const int g   = lid >> 2;
    const int tig = lid & 3;
    const int warp_m = wid & 1;
    const int warp_n = wid >> 1;

    const int rowBase = blockIdx.y * 128;
    const int colBase = blockIdx.x * BN;

    float acc[4][NT][4];
#pragma unroll
    for (int mt = 0; mt < 4; mt++)
#pragma unroll
        for (int nt = 0; nt < NT; nt++)
#pragma unroll
            for (int i = 0; i < 4; i++) acc[mt][nt][i] = 0.f;

    float4 aRegF[4];
    uint4  aRegH[2];
    float2 wReg[NB2];

    auto loadA = [&](int k0) {
        if (HIN) {
            const __half* A = (const __half*)Ain;
#pragma unroll
            for (int i = 0; i < 2; i++) {
                int idx = tid + 256 * i;
                int m = idx >> 2, c8 = idx & 3;
                int gr = rowBase + m;
                aRegH[i] = (gr < M) ? *(const uint4*)(A + (size_t)gr * K + k0 + c8 * 8)
                                    : make_uint4(0u, 0u, 0u, 0u);
            }
        } else {
            const float* A = (const float*)Ain;
#pragma unroll
            for (int i = 0; i < 4; i++) {
                int idx = tid + 256 * i;
                int m = idx >> 3, c4 = idx & 7;
                int gr = rowBase + m;
                aRegF[i] = (gr < M) ? *(const float4*)(A + (size_t)gr * K + k0 + c4 * 4)
                                    : make_float4(0.f, 0.f, 0.f, 0.f);
            }
        }
    };
    auto loadW = [&](int k0) {
#pragma unroll
        for (int i = 0; i < NB2; i++) {
            int idx = tid + 256 * i;
            int n  = idx & (BN - 1);
            int k2 = idx >> LOG2BN;
            wReg[i].x = W[(size_t)(k0 + 2 * k2)     * Nc + colBase + n];
            wReg[i].y = W[(size_t)(k0 + 2 * k2 + 1) * Nc + colBase + n];
        }
    };
    auto stsTiles = [&]() {
        if (HIN) {
#pragma unroll
            for (int i = 0; i < 2; i++) {
                int idx = tid + 256 * i;
                int m = idx >> 2, c8 = idx & 3;
                *(uint4*)(sA + m * SAW + c8 * 4) = aRegH[i];
            }
        } else {
#pragma unroll
            for (int i = 0; i < 4; i++) {
                int idx = tid + 256 * i;
                int m = idx >> 3, c4 = idx & 7;
                float4 v = aRegF[i];
                uint2 w;
                w.x = pack_half2(v.x, v.y);
                w.y = pack_half2(v.z, v.w);
                *(uint2*)(sA + m * SAW + c4 * 2) = w;
            }
        }
#pragma unroll
        for (int i = 0; i < NB2; i++) {
            int idx = tid + 256 * i;
            int n  = idx & (BN - 1);
            int k2 = idx >> LOG2BN;
            sB[k2 * SBW + n] = pack_half2(wReg[i].x, wReg[i].y);
        }
    };

    const int nchunk = K / 32;
    loadA(0);
    loadW(0);

    for (int ch = 0; ch < nchunk; ch++) {
        stsTiles();
        __syncthreads();
        if (ch + 1 < nchunk) { loadA((ch + 1) * 32); loadW((ch + 1) * 32); }

#pragma unroll
        for (int kk = 0; kk < 2; kk++) {
            const int kb2 = kk * 8;
            uint32_t afr[4][4];
#pragma unroll
            for (int mt = 0; mt < 4; mt++) {
                int m = warp_m * 64 + mt * 16 + g;
                afr[mt][0] = sA[(m)     * SAW + kb2 + tig];
                afr[mt][1] = sA[(m + 8) * SAW + kb2 + tig];
                afr[mt][2] = sA[(m)     * SAW + kb2 + tig + 4];
                afr[mt][3] = sA[(m + 8) * SAW + kb2 + tig + 4];
            }
            uint32_t bfr[NT][2];
#pragma unroll
            for (int nt = 0; nt < NT; nt++) {
                int n = warp_n * (BN / 4) + nt * 8 + g;
                bfr[nt][0] = sB[(kb2 + tig)     * SBW + n];
                bfr[nt][1] = sB[(kb2 + tig + 4) * SBW + n];
            }
#pragma unroll
            for (int mt = 0; mt < 4; mt++)
#pragma unroll
                for (int nt = 0; nt < NT; nt++)
                    mma_f16_16x8x16(acc[mt][nt], afr[mt], bfr[nt]);
        }
        __syncthreads();
    }

    if (AH > 0) {
        const int h = (AH == 1) ? 0 : ((colBase + warp_n * (BN / 4)) >> 6);
#pragma unroll
        for (int mt = 0; mt < 4; mt++) {
            float s0 = 0.f, s1 = 0.f, d0 = 0.f, d1 = 0.f;
#pragma unroll
            for (int nt = 0; nt < NT; nt++) {
                int col = colBase + warp_n * (BN / 4) + nt * 8 + tig * 2;
                float a0 = avs[col], a1 = avs[col + 1];
                float b0 = avd[col], b1 = avd[col + 1];
                s0 += acc[mt][nt][0] * a0 + acc[mt][nt][1] * a1;
                s1 += acc[mt][nt][2] * a0 + acc[mt][nt][3] * a1;
                d0 += acc[mt][nt][0] * b0 + acc[mt][nt][1] * b1;
                d1 += acc[mt][nt][2] * b0 + acc[mt][nt][3] * b1;
            }
#pragma unroll
            for (int off = 1; off <= 2; off <<= 1) {
                s0 += __shfl_xor_sync(0xFFFFFFFFu, s0, off);
                s1 += __shfl_xor_sync(0xFFFFFFFFu, s1, off);
                d0 += __shfl_xor_sync(0xFFFFFFFFu, d0, off);
                d1 += __shfl_xor_sync(0xFFFFFFFFu, d1, off);
            }
            if (tig == 0) {
                int row0 = rowBase + warp_m * 64 + mt * 16 + g;
                int row1 = row0 + 8;
                if (row0 < M) {
                    atomicAdd(&as_n[(size_t)row0 * AH + h], s0);
                    atomicAdd(&ad_n[(size_t)row0 * AH + h], d0);
                }
                if (row1 < M) {
                    atomicAdd(&as_n[(size_t)row1 * AH + h], s1);
                    atomicAdd(&ad_n[(size_t)row1 * AH + h], d1);
                }
            }
        }
    }

#pragma unroll
    for (int mt = 0; mt < 4; mt++) {
        int row0 = rowBase + warp_m * 64 + mt * 16 + g;
        int row1 = row0 + 8;
#pragma unroll
        for (int nt = 0; nt < NT; nt++) {
            int col = colBase + warp_n * (BN / 4) + nt * 8 + tig * 2;
            float bx = 0.f, by = 0.f;
            if (bias) { bx = bias[col]; by = bias[col + 1]; }
            float2 v0 = make_float2(acc[mt][nt][0] + bx, acc[mt][nt][1] + by);
            float2 v1 = make_float2(acc[mt][nt][2] + bx, acc[mt][nt][3] + by);
            if (do_relu) {
                v0.x = fmaxf(v0.x, 0.f); v0.y = fmaxf(v0.y, 0.f);
                v1.x = fmaxf(v1.x, 0.f); v1.y = fmaxf(v1.y, 0.f);
            }
            if (HOUT) {
                __half2* Ch = (__half2*)Cout;
                if (row0 < M) Ch[((size_t)row0 * Nc + col) >> 1] = __float22half2_rn(v0);
                if (row1 < M) Ch[((size_t)row1 * Nc + col) >> 1] = __float22half2_rn(v1);
            } else {
                float* Cf = (float*)Cout;
                if (row0 < M) *(float2*)(Cf + (size_t)row0 * Nc + col) = v0;
                if (row1 < M) *(float2*)(Cf + (size_t)row1 * Nc + col) = v1;
            }
        }
    }
}

// ---------------- CSR build ----------------
__global__ void count_kernel(const int* __restrict__ ei, int E, int N, int* __restrict__ deg)
{
    int base = (blockIdx.x * blockDim.x + threadIdx.x) * 4;
    int ET = E + N;
    if (base >= ET) return;
    if (base + 3 < E) {
        int4 d4 = *(const int4*)(ei + E + base);
        atomicAdd(&deg[d4.x], 1);
        atomicAdd(&deg[d4.y], 1);
        atomicAdd(&deg[d4.z], 1);
        atomicAdd(&deg[d4.w], 1);
    } else {
#pragma unroll
        for (int k = 0; k < 4; k++) {
            int e = base + k;
            if (e >= ET) break;
            int d = (e < E) ? ei[E + e] : (e - E);
            atomicAdd(&deg[d], 1);
        }
    }
}

__global__ void scan1_kernel(const int* __restrict__ deg, int* __restrict__ rowptr,
                             int* __restrict__ bsum, int N)
{
    __shared__ int sh[1024];
    int i = blockIdx.x * 1024 + threadIdx.x;
    int v = (i < N) ? deg[i] : 0;
    sh[threadIdx.x] = v;
    __syncthreads();
#pragma unroll
    for (int off = 1; off < 1024; off <<= 1) {
        int t = (threadIdx.x >= off) ? sh[threadIdx.x - off] : 0;
        __syncthreads();
        sh[threadIdx.x] += t;
        __syncthreads();
    }
    if (i < N) rowptr[i + 1] = sh[threadIdx.x];
    if (threadIdx.x == 1023) bsum[blockIdx.x] = sh[1023];
}

// scan3: finalize rowptr AND init fill cursor cur[i] = rowptr[i]
__global__ void scan3_kernel(int* __restrict__ rowptr, const int* __restrict__ bsum,
                             const int* __restrict__ deg, int* __restrict__ cur, int N)
{
    int off = 0;
    for (int b = 0; b < blockIdx.x; b++) off += bsum[b];
    int i = blockIdx.x * 1024 + threadIdx.x;
    if (i < N) {
        int v = rowptr[i + 1] + off;
        rowptr[i + 1] = v;
        cur[i] = v - deg[i];
    }
    if (i == 0) rowptr[0] = 0;
}

__global__ void fill_kernel(const int* __restrict__ ei, int E, int N,
                            int* __restrict__ cur, int* __restrict__ adj)
{
    int base = (blockIdx.x * blockDim.x + threadIdx.x) * 4;
    int ET = E + N;
    if (base >= ET) return;
    if (base + 3 < E) {
        int4 s4 = *(const int4*)(ei + base);
        int4 d4 = *(const int4*)(ei + E + base);
        int p0 = atomicAdd(&cur[d4.x], 1);
        int p1 = atomicAdd(&cur[d4.y], 1);
        int p2 = atomicAdd(&cur[d4.z], 1);
        int p3 = atomicAdd(&cur[d4.w], 1);
        adj[p0] = s4.x;
        adj[p1] = s4.y;
        adj[p2] = s4.z;
        adj[p3] = s4.w;
    } else {
#pragma unroll
        for (int k = 0; k < 4; k++) {
            int e = base + k;
            if (e >= ET) break;
            int s, d;
            if (e < E) { s = ei[e]; d = ei[E + e]; } else { s = d = e - E; }
            int pos = atomicAdd(&cur[d], 1);
            adj[pos] = s;
        }
    }
}

// ---------------- fused gather (1 warp/node, vectorized adj, half in/out) --------
__global__ __launch_bounds__(256) void gat_gather4_kernel(
    const int* __restrict__ rowptr, const int* __restrict__ adj,
    const __half* __restrict__ xl,
    const float* __restrict__ as_n, const float* __restrict__ ad_n,
    const float* __restrict__ bias, __half* __restrict__ out, int N)
{
    int w = (blockIdx.x * blockDim.x + threadIdx.x) >> 5;
    int lane = threadIdx.x & 31;
    if (w >= N) return;

    const int h   = lane >> 3;
    const int col = lane * 8;
    const float ad = ad_n[(size_t)w * 4 + h];

    float acc[8];
#pragma unroll
    for (int i = 0; i < 8; i++) acc[i] = 0.f;
    float den = 0.f;

    const int beg = rowptr[w], end = rowptr[w + 1];
    int j = beg;
    // peel to 4-alignment so int4 adj loads are aligned
    int pre = (4 - (beg & 3)) & 3;
    if (pre > end - beg) pre = end - beg;
    for (int k = 0; k < pre; k++, j++) {
        int s = adj[j];
        float a = edge_alpha(as_n[(size_t)s * 4 + h], ad);
        uint4 r = *(const uint4*)(xl + (size_t)s * 256 + col);
        den += a;
        acc8_half(acc, a, r);
    }
    for (; j + 3 < end; j += 4) {
        int4 s4 = *(const int4*)(adj + j);     // lane-invariant LDG.128 broadcast
        float a0 = edge_alpha(as_n[(size_t)s4.x * 4 + h], ad);
        float a1 = edge_alpha(as_n[(size_t)s4.y * 4 + h], ad);
        float a2 = edge_alpha(as_n[(size_t)s4.z * 4 + h], ad);
        float a3 = edge_alpha(as_n[(size_t)s4.w * 4 + h], ad);
        uint4 r0 = *(const uint4*)(xl + (size_t)s4.x * 256 + col);
        uint4 r1 = *(const uint4*)(xl + (size_t)s4.y * 256 + col);
        uint4 r2 = *(const uint4*)(xl + (size_t)s4.z * 256 + col);
        uint4 r3 = *(const uint4*)(xl + (size_t)s4.w * 256 + col);
        den += (a0 + a1) + (a2 + a3);
        acc8_half(acc, a0, r0);
        acc8_half(acc, a1, r1);
        acc8_half(acc, a2, r2);
        acc8_half(acc, a3, r3);
    }
    for (; j < end; j++) {
        int s = adj[j];
        float a = edge_alpha(as_n[(size_t)s * 4 + h], ad);
        uint4 r = *(const uint4*)(xl + (size_t)s * 256 + col);
        den += a;
        acc8_half(acc, a, r);
    }

    float inv = 1.f / (den + 1e-16f);
    __half2 o[4];
#pragma unroll
    for (int i = 0; i < 4; i++) {
        float2 f;
        f.x = fmaxf(acc[2 * i]     * inv + bias[col + 2 * i],     0.f);
        f.y = fmaxf(acc[2 * i + 1] * inv + bias[col + 2 * i + 1], 0.f);
        o[i] = __float22half2_rn(f);
    }
    *(uint4*)(out + (size_t)w * 256 + col) = *(const uint4*)o;
}

__global__ __launch_bounds__(256) void gat_gather1_kernel(
    const int* __restrict__ rowptr, const int* __restrict__ adj,
    const __half* __restrict__ xl,
    const float* __restrict__ as_n, const float* __restrict__ ad_n,
    const float* __restrict__ bias, __half* __restrict__ out, int N)
{
    int w = (blockIdx.x * blockDim.x + threadIdx.x) >> 5;
    int lane = threadIdx.x & 31;
    if (w >= N) return;

    const int col = lane * 2;
    const float ad = ad_n[w];

    float acc0 = 0.f, acc1 = 0.f, den = 0.f;

    const int beg = rowptr[w], end = rowptr[w + 1];
    int j = beg;
    int pre = (4 - (beg & 3)) & 3;
    if (pre > end - beg) pre = end - beg;
    for (int k = 0; k < pre; k++, j++) {
        int s = adj[j];
        float a = edge_alpha(as_n[s], ad);
        float2 f = __half22float2(*(const __half2*)(xl + (size_t)s * 64 + col));
        den += a;
        acc0 += a * f.x;
        acc1 += a * f.y;
    }
    for (; j + 3 < end; j += 4) {
        int4 s4 = *(const int4*)(adj + j);
        float a0 = edge_alpha(as_n[s4.x], ad);
        float a1 = edge_alpha(as_n[s4.y], ad);
        float a2 = edge_alpha(as_n[s4.z], ad);
        float a3 = edge_alpha(as_n[s4.w], ad);
        float2 f0 = __half22float2(*(const __half2*)(xl + (size_t)s4.x * 64 + col));
        float2 f1 = __half22float2(*(const __half2*)(xl + (size_t)s4.y * 64 + col));
        float2 f2 = __half22float2(*(const __half2*)(xl + (size_t)s4.z * 64 + col));
        float2 f3 = __half22float2(*(const __half2*)(xl + (size_t)s4.w * 64 + col));
        den += (a0 + a1) + (a2 + a3);
        acc0 += a0 * f0.x + a1 * f1.x + a2 * f2.x + a3 * f3.x;
        acc1 += a0 * f0.y + a1 * f1.y + a2 * f2.y + a3 * f3.y;
    }
    for (; j < end; j++) {
        int s = adj[j];
        float a = edge_alpha(as_n[s], ad);
        float2 f = __half22float2(*(const __half2*)(xl + (size_t)s * 64 + col));
        den += a;
        acc0 += a * f.x;
        acc1 += a * f.y;
    }

    float inv = 1.f / (den + 1e-16f);
    float2 f;
    f.x = fmaxf(acc0 * inv + bias[col + 0], 0.f);
    f.y = fmaxf(acc1 * inv + bias[col + 1], 0.f);
    *(__half2*)(out + (size_t)w * 64 + col) = __float22half2_rn(f);
}

// ---------------- host orchestration ----------------
extern "C" void kernel_launch(void* const* d_in, const int* in_sizes, int n_in,
                              void* d_out, int out_size)
{
    const float* x   = (const float*)d_in[0];
    const int*   ei  = (const int*)d_in[1];
    const float* W1  = (const float*)d_in[2];
    const float* as1 = (const float*)d_in[3];
    const float* ad1 = (const float*)d_in[4];
    const float* b1  = (const float*)d_in[5];
    const float* W2  = (const float*)d_in[6];
    const float* as2 = (const float*)d_in[7];
    const float* ad2 = (const float*)d_in[8];
    const float* b2  = (const float*)d_in[9];
    const float* W3  = (const float*)d_in[10];
    const float* as3 = (const float*)d_in[11];
    const float* ad3 = (const float*)d_in[12];
    const float* b3  = (const float*)d_in[13];
    const float* Wfc = (const float*)d_in[14];
    const float* bfc = (const float*)d_in[15];
    float* out = (float*)d_out;

    int N  = in_sizes[0] / kIN;
    int E  = in_sizes[1] / 2;
    int ET = E + N;

    float *bufA, *bufB, *bufC, *attn;
    int *rowptr, *deg, *cur, *adj, *bsum;
    cudaGetSymbolAddress((void**)&bufA, g_bufA);
    cudaGetSymbolAddress((void**)&bufB, g_bufB);
    cudaGetSymbolAddress((void**)&bufC, g_bufC);
    cudaGetSymbolAddress((void**)&attn, g_attn);
    cudaGetSymbolAddress((void**)&rowptr, g_rowptr);
    cudaGetSymbolAddress((void**)&deg,    g_deg);
    cudaGetSymbolAddress((void**)&cur,    g_cur);
    cudaGetSymbolAddress((void**)&adj,    g_adj);
    cudaGetSymbolAddress((void**)&bsum,   g_bsum);

    size_t NH = (size_t)N * kH;
    float* pas1 = attn;
    float* pad1 = attn + NH;
    float* pas2 = attn + 2 * NH;
    float* pad2 = attn + 3 * NH;
    float* pas3 = attn + 4 * NH;
    float* pad3 = attn + 5 * NH;

    __half* bufAh = (__half*)bufA;
    __half* bufBh = (__half*)bufB;
    __half* bufCh = (__half*)bufC;

    int edge4Blocks = (ET + 1023) / 1024;
    int gBlocks = (N + 7) / 8;
    int scanBlocks = (N + 1023) / 1024;

    dim3 grid256(2, (N + 127) / 128);
    dim3 grid64(1, (N + 127) / 128);
    dim3 gridFC(4, (N + 127) / 128);

    static cudaStream_t s2 = nullptr;
    static cudaEvent_t evFork = nullptr, evJoin = nullptr;
    if (!s2) {
        cudaStreamCreateWithFlags(&s2, cudaStreamNonBlocking);
        cudaEventCreateWithFlags(&evFork, cudaEventDisableTiming);
        cudaEventCreateWithFlags(&evJoin, cudaEventDisableTiming);
    }

    // attn zeroing precedes all GEMM epilogue atomics (main stream)
    cudaMemsetAsync(attn, 0, 6 * NH * sizeof(float));
    cudaEventRecord(evFork, 0);
    cudaStreamWaitEvent(s2, evFork, 0);

    // ---- CSR build on s2 (overlaps GEMM1) ----
    cudaMemsetAsync(deg, 0, (size_t)N * sizeof(int), s2);
    count_kernel<<<edge4Blocks, 256, 0, s2>>>(ei, E, N, deg);
    scan1_kernel<<<scanBlocks, 1024, 0, s2>>>(deg, rowptr, bsum, N);
    scan3_kernel<<<scanBlocks, 1024, 0, s2>>>(rowptr, bsum, deg, cur, N);
    fill_kernel<<<edge4Blocks, 256, 0, s2>>>(ei, E, N, cur, adj);
    cudaEventRecord(evJoin, s2);

    // ---- layer 1 GEMM (independent of CSR) ----
    tgemm_kernel<128, 4, false, true><<<grid256, 256>>>(
        x, W1, bufA, N, kIN, kHC, nullptr, 0, as1, ad1, pas1, pad1);
    cudaStreamWaitEvent(0, evJoin, 0);

    gat_gather4_kernel<<<gBlocks, 256>>>(rowptr, adj, bufAh, pas1, pad1, b1, bufBh, N);

    // ---- layer 2 ----
    tgemm_kernel<128, 4, true, true><<<grid256, 256>>>(
        bufBh, W2, bufA, N, kHC, kHC, nullptr, 0, as2, ad2, pas2, pad2);
    gat_gather4_kernel<<<gBlocks, 256>>>(rowptr, adj, bufAh, pas2, pad2, b2, bufCh, N);

    // ---- layer 3 ----
    tgemm_kernel<64, 1, true, true><<<grid64, 256>>>(
        bufCh, W3, bufA, N, kHC, kC, nullptr, 0, as3, ad3, pas3, pad3);
    gat_gather1_kernel<<<gBlocks, 256>>>(rowptr, adj, bufAh, pas3, pad3, b3, bufBh, N);

    // ---- final fc ----
    tgemm_kernel<128, 0, true, false><<<gridFC, 256>>>(
        bufBh, Wfc, out, N, kC, kOUT, bfc, 1, nullptr, nullptr, nullptr, nullptr);
}